// round 1
// baseline (speedup 1.0000x reference)
#include <cuda_runtime.h>
#include <cuda_bf16.h>
#include <cstdint>

// Problem constants (fixed by the reference)
constexpr int B_  = 4;
constexpr int C_  = 256;
constexpr int H_  = 64;
constexpr int W_  = 64;
constexpr int Co_ = 256;
constexpr int K_  = 9;       // 3x3 taps
constexpr int HoWo = 64 * 64;            // 4096
constexpr int F_  = C_ * K_;             // 2304
constexpr int N_  = B_ * HoWo;           // 16384

// Scratch: im2col matrix, [F_, N_] row-major = 2304 * 16384 floats = 151 MB
__device__ float g_cols[(size_t)F_ * N_];

// ---------------------------------------------------------------------------
// Kernel 1: deformable im2col.
// One thread per (b, k, ho, wo). Computes bilinear sample coords once, then
// loops over C channels. Writes cols[(c*9+k)][b*4096+p], coalesced along p.
// ---------------------------------------------------------------------------
__global__ __launch_bounds__(256) void im2col_deform(
    const float* __restrict__ x,       // [B, C, H, W]
    const float* __restrict__ off,     // [B, 18, Ho, Wo]
    float* __restrict__ cols)          // [F, N]
{
    int idx = blockIdx.x * blockDim.x + threadIdx.x;
    if (idx >= B_ * K_ * HoWo) return;

    int p  = idx & 4095;         // ho*64+wo
    int bk = idx >> 12;
    int k  = bk % K_;
    int b  = bk / K_;
    int ho = p >> 6;
    int wo = p & 63;
    int ki = k / 3;
    int kj = k % 3;

    // offset channels: 2k = y, 2k+1 = x
    float sy = off[((size_t)(b * 18 + 2 * k)     ) * HoWo + p] + (float)(ho - 1 + ki);
    float sx = off[((size_t)(b * 18 + 2 * k + 1) ) * HoWo + p] + (float)(wo - 1 + kj);

    float y0f = floorf(sy);
    float x0f = floorf(sx);
    float dy = sy - y0f;
    float dx = sx - x0f;
    int y0 = (int)y0f, x0 = (int)x0f;
    int y1 = y0 + 1,  x1 = x0 + 1;

    bool vy0 = (y0 >= 0) & (y0 < H_);
    bool vy1 = (y1 >= 0) & (y1 < H_);
    bool vx0 = (x0 >= 0) & (x0 < W_);
    bool vx1 = (x1 >= 0) & (x1 < W_);

    float w00 = (1.f - dy) * (1.f - dx) * (float)(vy0 && vx0);
    float w01 = (1.f - dy) * dx         * (float)(vy0 && vx1);
    float w10 = dy * (1.f - dx)         * (float)(vy1 && vx0);
    float w11 = dy * dx                 * (float)(vy1 && vx1);

    int y0c = min(max(y0, 0), H_ - 1);
    int y1c = min(max(y1, 0), H_ - 1);
    int x0c = min(max(x0, 0), W_ - 1);
    int x1c = min(max(x1, 0), W_ - 1);

    int l00 = y0c * W_ + x0c;
    int l01 = y0c * W_ + x1c;
    int l10 = y1c * W_ + x0c;
    int l11 = y1c * W_ + x1c;

    const float* xb = x + (size_t)b * C_ * HoWo;
    float* colp = cols + (size_t)k * N_ + (size_t)b * HoWo + p;

    #pragma unroll 4
    for (int c = 0; c < C_; c++) {
        const float* xc = xb + (size_t)c * HoWo;
        float v = w00 * __ldg(&xc[l00]) + w01 * __ldg(&xc[l01])
                + w10 * __ldg(&xc[l10]) + w11 * __ldg(&xc[l11]);
        colp[(size_t)c * K_ * N_] = v;   // f = c*9 + k
    }
}

// ---------------------------------------------------------------------------
// Kernel 2: SGEMM  out[co][n] = sum_f W[co][f] * cols[f][n]
// M=256, N=16384, K(F)=2304. 128x128 tile, BK=16, 256 threads, 8x8/thread.
// Epilogue scatters n -> (b, p) so output is [B, Co, Ho, Wo].
// ---------------------------------------------------------------------------
__global__ __launch_bounds__(256) void sgemm_deform(
    const float* __restrict__ Wt,      // [Co, F]
    const float* __restrict__ cols,    // [F, N]
    float* __restrict__ out)           // [B, Co, HoWo]
{
    __shared__ float As[16][128];
    __shared__ float Bs[16][128];

    int t  = threadIdx.x;
    int m0 = blockIdx.y * 128;
    int n0 = blockIdx.x * 128;
    int tx = t & 15;
    int ty = t >> 4;

    float acc[8][8] = {};

    for (int k0 = 0; k0 < F_; k0 += 16) {
        // Load A tile (transposed into As[k][m])
        #pragma unroll
        for (int it = 0; it < 2; it++) {
            int q   = t + it * 256;       // 0..511
            int row = q & 127;
            int kq  = (q >> 7) * 4;
            float4 w = *(const float4*)&Wt[(size_t)(m0 + row) * F_ + k0 + kq];
            As[kq + 0][row] = w.x;
            As[kq + 1][row] = w.y;
            As[kq + 2][row] = w.z;
            As[kq + 3][row] = w.w;
        }
        // Load B tile
        #pragma unroll
        for (int it = 0; it < 2; it++) {
            int q  = t + it * 256;
            int kr = q >> 5;              // 0..15
            int nc = (q & 31) * 4;        // 0..124
            *(float4*)&Bs[kr][nc] =
                *(const float4*)&cols[(size_t)(k0 + kr) * N_ + n0 + nc];
        }
        __syncthreads();

        #pragma unroll
        for (int kk = 0; kk < 16; kk++) {
            float a[8], bq[8];
            *(float4*)&a[0]  = *(const float4*)&As[kk][ty * 8];
            *(float4*)&a[4]  = *(const float4*)&As[kk][ty * 8 + 4];
            *(float4*)&bq[0] = *(const float4*)&Bs[kk][tx * 8];
            *(float4*)&bq[4] = *(const float4*)&Bs[kk][tx * 8 + 4];
            #pragma unroll
            for (int i = 0; i < 8; i++)
                #pragma unroll
                for (int j = 0; j < 8; j++)
                    acc[i][j] += a[i] * bq[j];
        }
        __syncthreads();
    }

    // Epilogue: n = n0 + tx*8 .. +7 all in same batch (4096 % 128 == 0)
    int n_base = n0 + tx * 8;
    int b = n_base >> 12;
    int p = n_base & 4095;
    #pragma unroll
    for (int i = 0; i < 8; i++) {
        int co = m0 + ty * 8 + i;
        float* op = out + ((size_t)(b * Co_ + co)) * HoWo + p;
        *(float4*)&op[0] = *(float4*)&acc[i][0];
        *(float4*)&op[4] = *(float4*)&acc[i][4];
    }
}

// ---------------------------------------------------------------------------
extern "C" void kernel_launch(void* const* d_in, const int* in_sizes, int n_in,
                              void* d_out, int out_size)
{
    const float* x      = (const float*)d_in[0];   // [4,256,64,64]
    const float* offset = (const float*)d_in[1];   // [4,18,64,64]
    const float* weight = (const float*)d_in[2];   // [256,256,3,3]
    float* out = (float*)d_out;                    // [4,256,64,64]

    float* cols;
    cudaGetSymbolAddress((void**)&cols, g_cols);

    {
        int total = B_ * K_ * HoWo;                // 147456
        int threads = 256;
        int blocks = (total + threads - 1) / threads;
        im2col_deform<<<blocks, threads>>>(x, offset, cols);
    }
    {
        dim3 grid(N_ / 128, Co_ / 128);            // (128, 2)
        sgemm_deform<<<grid, 256>>>(weight, cols, out);
    }
}

// round 4
// speedup vs baseline: 3.8072x; 3.8072x over previous
#include <cuda_runtime.h>
#include <cstdint>

// ---------------------------------------------------------------------------
// Problem constants
// ---------------------------------------------------------------------------
constexpr int B_   = 4;
constexpr int C_   = 256;
constexpr int H_   = 64;
constexpr int W_   = 64;
constexpr int Co_  = 256;
constexpr int HW_  = 64 * 64;           // 4096
constexpr int F_   = C_ * 9;            // 2304  (f' = k*256 + c ordering)
constexpr int N_   = B_ * HW_;          // 16384

// Scratch
__device__ __align__(1024) float g_colsT[(size_t)N_ * F_];     // [n][f'] 151MB
__device__ __align__(1024) float g_xt[(size_t)B_ * HW_ * C_];  // NHWC    16.8MB
__device__ __align__(1024) float g_wt[(size_t)Co_ * F_];       // [co][k*256+c]

// ---------------------------------------------------------------------------
// Helpers
// ---------------------------------------------------------------------------
__device__ __forceinline__ uint32_t smem_u32(const void* p) {
    uint32_t a;
    asm("{ .reg .u64 t; cvta.to.shared.u64 t, %1; cvt.u32.u64 %0, t; }" : "=r"(a) : "l"(p));
    return a;
}
__device__ __forceinline__ float to_tf32(float x) {
    uint32_t y;
    asm("cvt.rna.tf32.f32 %0, %1;" : "=r"(y) : "f"(x));
    return __uint_as_float(y);
}
__device__ __forceinline__ void cp_async16(uint32_t dst, const void* src) {
    asm volatile("cp.async.cg.shared.global [%0], [%1], 16;" :: "r"(dst), "l"(src));
}
#define CP_COMMIT() asm volatile("cp.async.commit_group;" ::: "memory")
#define CP_WAIT1()  asm volatile("cp.async.wait_group 1;" ::: "memory")

#define LDSM_X4(r0, r1, r2, r3, addr)                                          \
    asm volatile("ldmatrix.sync.aligned.m8n8.x4.shared.b16 {%0,%1,%2,%3}, [%4];" \
                 : "=r"(r0), "=r"(r1), "=r"(r2), "=r"(r3) : "r"(addr))

#define MMA_TF32(d, a, b0, b1)                                                 \
    asm volatile("mma.sync.aligned.m16n8k8.row.col.f32.tf32.tf32.f32 "         \
                 "{%0,%1,%2,%3},{%4,%5,%6,%7},{%8,%9},{%0,%1,%2,%3};"          \
                 : "+f"((d)[0]), "+f"((d)[1]), "+f"((d)[2]), "+f"((d)[3])      \
                 : "r"((a)[0]), "r"((a)[1]), "r"((a)[2]), "r"((a)[3]),         \
                   "r"(b0), "r"(b1))

// ---------------------------------------------------------------------------
// Kernel 1: x NCHW -> NHWC  (x_t[b][l][c])
// ---------------------------------------------------------------------------
__global__ __launch_bounds__(256) void transpose_x(const float* __restrict__ x,
                                                   float* __restrict__ xt) {
    __shared__ float t[32][33];
    int b = blockIdx.z, c0 = blockIdx.y * 32, l0 = blockIdx.x * 32;
    int tx = threadIdx.x & 31, ty = threadIdx.x >> 5;
    const float* xb = x + ((size_t)b * C_ + c0) * HW_;
    #pragma unroll
    for (int j = 0; j < 32; j += 8)
        t[ty + j][tx] = xb[(size_t)(ty + j) * HW_ + l0 + tx];
    __syncthreads();
    float* xo = xt + ((size_t)b * HW_ + l0) * C_;
    #pragma unroll
    for (int j = 0; j < 32; j += 8)
        xo[(size_t)(ty + j) * C_ + c0 + tx] = t[tx][ty + j];
}

// ---------------------------------------------------------------------------
// Kernel 2: weight [co][c][k] -> W_t [co][k*256+c], tf32-rounded
// ---------------------------------------------------------------------------
__global__ __launch_bounds__(256) void transpose_w(const float* __restrict__ w,
                                                   float* __restrict__ wt) {
    int co = blockIdx.x;
    const float* wi = w + (size_t)co * F_;
    float* wo = wt + (size_t)co * F_;
    for (int i = threadIdx.x; i < F_; i += 256) {
        int c = i / 9, kk = i % 9;
        wo[kk * 256 + c] = to_tf32(wi[i]);
    }
}

// ---------------------------------------------------------------------------
// Kernel 3: deformable im2col -> cols_T[n][k*256+c], tf32-rounded.
// Warp per (n, k); lanes cover channels (float4 each). Coalesced both ways.
// ---------------------------------------------------------------------------
__global__ __launch_bounds__(256) void im2col_t(const float* __restrict__ xt,
                                                const float* __restrict__ off,
                                                float* __restrict__ colsT) {
    int g    = blockIdx.x * 8 + (threadIdx.x >> 5);   // (n*9 + k)
    int lane = threadIdx.x & 31;
    int n = g / 9, k = g - n * 9;
    int b = n >> 12, p = n & 4095;
    int ho = p >> 6, wo = p & 63;
    int ki = k / 3, kj = k - ki * 3;

    float sy = off[((size_t)(b * 18 + 2 * k))     * HW_ + p] + (float)(ho - 1 + ki);
    float sx = off[((size_t)(b * 18 + 2 * k + 1)) * HW_ + p] + (float)(wo - 1 + kj);

    float y0f = floorf(sy), x0f = floorf(sx);
    float dy = sy - y0f, dx = sx - x0f;
    int y0 = (int)y0f, x0 = (int)x0f, y1 = y0 + 1, x1 = x0 + 1;
    bool vy0 = (y0 >= 0) & (y0 < H_), vy1 = (y1 >= 0) & (y1 < H_);
    bool vx0 = (x0 >= 0) & (x0 < W_), vx1 = (x1 >= 0) & (x1 < W_);

    float w00 = (1.f - dy) * (1.f - dx) * (float)(vy0 && vx0);
    float w01 = (1.f - dy) * dx         * (float)(vy0 && vx1);
    float w10 = dy * (1.f - dx)         * (float)(vy1 && vx0);
    float w11 = dy * dx                 * (float)(vy1 && vx1);

    int y0c = min(max(y0, 0), H_ - 1), y1c = min(max(y1, 0), H_ - 1);
    int x0c = min(max(x0, 0), W_ - 1), x1c = min(max(x1, 0), W_ - 1);
    int l00 = y0c * W_ + x0c, l01 = y0c * W_ + x1c;
    int l10 = y1c * W_ + x0c, l11 = y1c * W_ + x1c;

    const float* xb = xt + (size_t)b * HW_ * C_;
    float* dst = colsT + (size_t)n * F_ + k * 256;

    #pragma unroll
    for (int c0 = 0; c0 < 256; c0 += 128) {
        int c = c0 + lane * 4;
        float4 a  = *(const float4*)&xb[(size_t)l00 * C_ + c];
        float4 bb = *(const float4*)&xb[(size_t)l01 * C_ + c];
        float4 cc = *(const float4*)&xb[(size_t)l10 * C_ + c];
        float4 dd = *(const float4*)&xb[(size_t)l11 * C_ + c];
        float4 v;
        v.x = to_tf32(w00 * a.x + w01 * bb.x + w10 * cc.x + w11 * dd.x);
        v.y = to_tf32(w00 * a.y + w01 * bb.y + w10 * cc.y + w11 * dd.y);
        v.z = to_tf32(w00 * a.z + w01 * bb.z + w10 * cc.z + w11 * dd.z);
        v.w = to_tf32(w00 * a.w + w01 * bb.w + w10 * cc.w + w11 * dd.w);
        *(float4*)&dst[c] = v;
    }
}

// ---------------------------------------------------------------------------
// Kernel 4: tf32 GEMM via mma.sync.m16n8k8 (sm_80 path, works on sm_100).
// out[co][n] = sum_f Wt[co][f] * colsT[n][f]
// CTA tile 128(M) x 128(N) x 32(K), 8 warps (warp tile 64x32), 3-stage cp.async.
// Both operands are k-contiguous in gmem; smem rows = 128B with XOR swizzle.
// ---------------------------------------------------------------------------
constexpr int BK      = 32;
constexpr int KITERS  = F_ / BK;            // 72
constexpr int A_SZ    = 128 * BK * 4;       // 16KB
constexpr int STG     = 2 * A_SZ;           // 32KB (A then B)
constexpr int STAGES  = 3;
constexpr int GEMM_SMEM = STAGES * STG;     // 96KB

__device__ __forceinline__ void g_load_stage(uint32_t st,
                                             const float* __restrict__ Wt,
                                             const float* __restrict__ colsT,
                                             int m0, int n0, int kg, int tid) {
    #pragma unroll
    for (int it = 0; it < 4; it++) {
        int u = tid + it * 256;
        int row = u >> 3, c16 = u & 7;
        uint32_t dst = st + row * 128 + ((c16 * 16) ^ ((row & 7) << 4));
        cp_async16(dst, Wt + (size_t)(m0 + row) * F_ + kg + c16 * 4);
    }
    #pragma unroll
    for (int it = 0; it < 4; it++) {
        int u = tid + it * 256;
        int row = u >> 3, c16 = u & 7;
        uint32_t dst = st + A_SZ + row * 128 + ((c16 * 16) ^ ((row & 7) << 4));
        cp_async16(dst, colsT + (size_t)(n0 + row) * F_ + kg + c16 * 4);
    }
}

__global__ __launch_bounds__(256, 2) void gemm_tf32(const float* __restrict__ Wt,
                                                    const float* __restrict__ colsT,
                                                    float* __restrict__ out) {
    extern __shared__ char smem[];
    uint32_t sb = smem_u32(smem);
    int tid = threadIdx.x, lane = tid & 31, warp = tid >> 5;
    int m0 = blockIdx.x * 128, n0 = blockIdx.y * 128;
    int mwarp = (warp & 1) * 64, nwarp = (warp >> 1) * 32;
    int sel = lane >> 3, row_in = lane & 7;

    // ldmatrix per-thread address components.
    // A fragment (m16k8): r0:(m0-7,k0-3) r1:(m8-15,k0-3) r2:(m0-7,k4-7) r3:(m8-15,k4-7)
    uint32_t aoff[4], ax[4];
    #pragma unroll
    for (int f = 0; f < 4; f++) {
        int m = mwarp + f * 16 + (sel & 1) * 8 + row_in;
        aoff[f] = (uint32_t)(m * 128);
        ax[f]   = (uint32_t)(((m & 7) << 4) ^ ((sel >> 1) * 16));
    }
    // B pair g covers n-frags 2g,2g+1: r0:(n0-7,k0-3) r1:(n0-7,k4-7) r2:(n8-15,k0-3) r3:(n8-15,k4-7)
    uint32_t boff[2], bx[2];
    #pragma unroll
    for (int g = 0; g < 2; g++) {
        int n = nwarp + g * 16 + (sel >> 1) * 8 + row_in;
        boff[g] = (uint32_t)(A_SZ + n * 128);
        bx[g]   = (uint32_t)(((n & 7) << 4) ^ ((sel & 1) * 16));
    }

    float acc[4][4][4];
    #pragma unroll
    for (int f = 0; f < 4; f++)
        #pragma unroll
        for (int j = 0; j < 4; j++)
            #pragma unroll
            for (int q = 0; q < 4; q++) acc[f][j][q] = 0.f;

    g_load_stage(sb,       Wt, colsT, m0, n0, 0,  tid); CP_COMMIT();
    g_load_stage(sb + STG, Wt, colsT, m0, n0, BK, tid); CP_COMMIT();

    int s = 0;
    for (int i = 0; i < KITERS; i++) {
        CP_WAIT1();
        __syncthreads();

        int jn = i + 2;
        if (jn < KITERS) {
            int sj = jn % 3;
            g_load_stage(sb + sj * STG, Wt, colsT, m0, n0, jn * BK, tid);
        }
        CP_COMMIT();

        uint32_t st = sb + s * STG;
        #pragma unroll
        for (int ks = 0; ks < 4; ks++) {
            uint32_t kb = ks * 32;
            uint32_t a[4][4], bb[2][4];
            #pragma unroll
            for (int f = 0; f < 4; f++)
                LDSM_X4(a[f][0], a[f][1], a[f][2], a[f][3],
                        st + aoff[f] + (kb ^ ax[f]));
            #pragma unroll
            for (int g = 0; g < 2; g++)
                LDSM_X4(bb[g][0], bb[g][1], bb[g][2], bb[g][3],
                        st + boff[g] + (kb ^ bx[g]));
            #pragma unroll
            for (int f = 0; f < 4; f++) {
                #pragma unroll
                for (int j = 0; j < 4; j++) {
                    MMA_TF32(acc[f][j], a[f],
                             bb[j >> 1][(j & 1) * 2], bb[j >> 1][(j & 1) * 2 + 1]);
                }
            }
        }
        if (++s == 3) s = 0;
    }

    // Epilogue: c0:(r, 2t) c1:(r, 2t+1) c2:(r+8, 2t) c3:(r+8, 2t+1)
    int tig = lane & 3, gid = lane >> 2;
    int b = n0 >> 12;
    int pbase = (n0 & 4095) + nwarp;
    #pragma unroll
    for (int f = 0; f < 4; f++) {
        #pragma unroll
        for (int j = 0; j < 4; j++) {
            int co = m0 + mwarp + f * 16 + gid;
            int p  = pbase + j * 8 + tig * 2;
            float* o0 = out + ((size_t)(b * Co_ + co)) * HW_ + p;
            *(float2*)o0 = make_float2(acc[f][j][0], acc[f][j][1]);
            *(float2*)(o0 + (size_t)8 * HW_) = make_float2(acc[f][j][2], acc[f][j][3]);
        }
    }
}

// ---------------------------------------------------------------------------
extern "C" void kernel_launch(void* const* d_in, const int* in_sizes, int n_in,
                              void* d_out, int out_size) {
    const float* x      = (const float*)d_in[0];
    const float* offset = (const float*)d_in[1];
    const float* weight = (const float*)d_in[2];
    float* out = (float*)d_out;

    float *colsT, *xt, *wt;
    cudaGetSymbolAddress((void**)&colsT, g_colsT);
    cudaGetSymbolAddress((void**)&xt, g_xt);
    cudaGetSymbolAddress((void**)&wt, g_wt);

    cudaFuncSetAttribute(gemm_tf32, cudaFuncAttributeMaxDynamicSharedMemorySize, GEMM_SMEM);

    {
        dim3 grid(HW_ / 32, C_ / 32, B_);
        transpose_x<<<grid, 256>>>(x, xt);
    }
    transpose_w<<<Co_, 256>>>(weight, wt);
    {
        int groups = N_ * 9;                   // 147456 warps
        im2col_t<<<groups / 8, 256>>>(xt, offset, colsT);
    }
    {
        dim3 grid(Co_ / 128, N_ / 128);        // (2, 128) — m fastest for L2 reuse
        gemm_tf32<<<grid, 256, GEMM_SMEM>>>(wt, colsT, out);
    }
}